// round 1
// baseline (speedup 1.0000x reference)
#include <cuda_runtime.h>

// Problem constants
#define HH 256
#define WW 256
#define WB 129          // WW/2 + 1
#define NB 16           // batch
#define NC 32           // in channels
#define NO 32           // out channels

// Scratch: frequency-domain buffers (device globals: allocation-free rule)
__device__ float2 g_Xf[(size_t)NB * NC * HH * WB];   // 135 MB
__device__ float2 g_Kf[(size_t)NO * NC * HH * WB];   // 270 MB
__device__ float2 g_Of[(size_t)NB * NO * HH * WB];   // 135 MB

// ---------------------------------------------------------------------------
// Shared twiddle table: tw[k] = exp(-2*pi*i*k/256), k = 0..127
// ---------------------------------------------------------------------------
__device__ __forceinline__ void fill_tw(float2* tw, int tid, int nthreads) {
    for (int k = tid; k < 128; k += nthreads) {
        float s_, c_;
        sincospif(-2.0f * (float)k / 256.0f, &s_, &c_);
        tw[k] = make_float2(c_, s_);
    }
}

// ---------------------------------------------------------------------------
// In-place 256-point complex FFT on a warp-private smem region s[0..255].
// dir = +1.0f : forward (use table as stored, e^{-i...})
// dir = -1.0f : inverse (conjugate twiddles), NO 1/N scaling applied here
// ---------------------------------------------------------------------------
__device__ __forceinline__ void warp_fft256(float2* s, const float2* tw,
                                            int lane, float dir) {
    // bit-reversal permutation (gather to regs, scatter to brev positions)
    float2 v[8];
#pragma unroll
    for (int k = 0; k < 8; k++) v[k] = s[lane + 32 * k];
    __syncwarp();
#pragma unroll
    for (int k = 0; k < 8; k++) {
        int idx = lane + 32 * k;
        s[__brev((unsigned)idx) >> 24] = v[k];
    }
    __syncwarp();

#pragma unroll
    for (int st = 0; st < 8; st++) {
        int half = 1 << st;
#pragma unroll
        for (int k = 0; k < 4; k++) {
            int j   = lane + 32 * k;          // butterfly id 0..127
            int pos = j & (half - 1);
            int i0  = ((j >> st) << (st + 1)) + pos;
            float2 w = tw[pos << (7 - st)];
            float wy = w.y * dir;
            float2 x0 = s[i0];
            float2 x1 = s[i0 + half];
            float2 t = make_float2(w.x * x1.x - wy * x1.y,
                                   w.x * x1.y + wy * x1.x);
            s[i0]        = make_float2(x0.x + t.x, x0.y + t.y);
            s[i0 + half] = make_float2(x0.x - t.x, x0.y - t.y);
        }
        __syncwarp();
    }
}

// ---------------------------------------------------------------------------
// Pass 1: forward real row FFT. One warp per row, 8 rows per block.
// in : real [nimg][256][256]
// out: complex [nimg][256][129]
// ---------------------------------------------------------------------------
__global__ void row_fft_kernel(const float* __restrict__ in,
                               float2* __restrict__ outf) {
    __shared__ float2 tw[128];
    __shared__ float2 rows[8][256];
    int tid = threadIdx.x, lane = tid & 31, wrp = tid >> 5;
    fill_tw(tw, tid, 256);

    size_t img = blockIdx.y;
    int row = blockIdx.x * 8 + wrp;
    const float* rp = in + (img * HH + row) * (size_t)WW;
    float2* s = rows[wrp];
#pragma unroll
    for (int k = 0; k < 8; k++)
        s[lane + 32 * k] = make_float2(rp[lane + 32 * k], 0.0f);
    __syncthreads();   // tw ready + row loaded

    warp_fft256(s, tw, lane, 1.0f);

    float2* op = outf + (img * HH + row) * (size_t)WB;
#pragma unroll
    for (int k = 0; k < 5; k++) {
        int idx = lane + 32 * k;
        if (idx < WB) op[idx] = s[idx];
    }
}

// ---------------------------------------------------------------------------
// Pass 2 / 4a: in-place column FFT over h for all 129 w-bins.
// Tiles of 8 columns per block; warp-per-column FFT.
// dir = +1 forward, -1 inverse (no scaling).
// ---------------------------------------------------------------------------
__global__ void col_fft_kernel(float2* __restrict__ buf, float dir) {
    __shared__ float2 tw[128];
    __shared__ float2 tile[8][258];   // pad 258 -> conflict-free load/store
    int tid = threadIdx.x;
    fill_tw(tw, tid, 256);

    size_t img = blockIdx.y;
    int col0 = blockIdx.x * 8;
    float2* base = buf + img * (size_t)(HH * WB);

    int c = tid & 7, r0 = tid >> 3;   // r0 in 0..31
    int col = col0 + c;
    if (col < WB) {
#pragma unroll
        for (int k = 0; k < 8; k++)
            tile[c][r0 + 32 * k] = base[(size_t)(r0 + 32 * k) * WB + col];
    }
    __syncthreads();

    int wrp = tid >> 5, lane = tid & 31;
    if (col0 + wrp < WB) warp_fft256(tile[wrp], tw, lane, dir);
    __syncthreads();

    if (col < WB) {
#pragma unroll
        for (int k = 0; k < 8; k++)
            base[(size_t)(r0 + 32 * k) * WB + col] = tile[c][r0 + 32 * k];
    }
}

// ---------------------------------------------------------------------------
// Pass 3: per-frequency-bin channel contraction.
//   Of[b,o,h,wb] = sum_c Xf[b,c,h,wb] * Kf[o,c,h,wb]   (complex multiply)
// Block = (h, tile of 8 w-bins). 512 threads: thread (b = t>>5, o = t&31).
// smem: Xs[c][bin][b] (32 KB), Ks[c][bin][o] (64 KB)  -> 96 KB dynamic.
// ---------------------------------------------------------------------------
__global__ void binconv_kernel(const float2* __restrict__ Xf,
                               const float2* __restrict__ Kf,
                               float2* __restrict__ Of) {
    extern __shared__ float2 sm[];
    float2* Xs = sm;                  // [(c*8+bin)*16 + b]
    float2* Ks = sm + 32 * 8 * 16;    // [(c*8+bin)*32 + o]

    int tid = threadIdx.x;            // 0..511
    int h = blockIdx.y;
    int wb0 = blockIdx.x * 8;
    int binl = tid & 7;
    int sub = tid >> 3;               // 0..63
    int wb = wb0 + binl;
    bool valid = (wb < WB);

    // load X: 512 images x 8 bins
#pragma unroll
    for (int i = 0; i < 8; i++) {
        int img = i * 64 + sub;
        int b = img >> 5, c = img & 31;
        float2 v = valid ? Xf[((size_t)img * HH + h) * WB + wb]
                         : make_float2(0.f, 0.f);
        Xs[(c * 8 + binl) * 16 + b] = v;
    }
    // load K: 1024 images x 8 bins
#pragma unroll
    for (int i = 0; i < 16; i++) {
        int img = i * 64 + sub;
        int o = img >> 5, c = img & 31;
        float2 v = valid ? Kf[((size_t)img * HH + h) * WB + wb]
                         : make_float2(0.f, 0.f);
        Ks[(c * 8 + binl) * 32 + o] = v;
    }
    __syncthreads();

    int o = tid & 31, b = tid >> 5;
    float2 acc[8];
#pragma unroll
    for (int q = 0; q < 8; q++) acc[q] = make_float2(0.f, 0.f);

#pragma unroll 4
    for (int c = 0; c < 32; c++) {
#pragma unroll
        for (int q = 0; q < 8; q++) {
            float2 xv = Xs[(c * 8 + q) * 16 + b];   // broadcast across lanes
            float2 kv = Ks[(c * 8 + q) * 32 + o];   // conflict-free
            acc[q].x += xv.x * kv.x - xv.y * kv.y;
            acc[q].y += xv.x * kv.y + xv.y * kv.x;
        }
    }

    size_t img = (size_t)b * NO + o;
    float2* op = Of + (img * HH + h) * (size_t)WB + wb0;
#pragma unroll
    for (int q = 0; q < 8; q++)
        if (wb0 + q < WB) op[q] = acc[q];
}

// ---------------------------------------------------------------------------
// Pass 4b: inverse real row FFT (irfft over w) + 1/(H*W) scaling.
// One warp per row; Hermitian reconstruction of bins 129..255.
// ---------------------------------------------------------------------------
__global__ void row_irfft_kernel(const float2* __restrict__ Of,
                                 float* __restrict__ out) {
    __shared__ float2 tw[128];
    __shared__ float2 rows[8][256];
    int tid = threadIdx.x, lane = tid & 31, wrp = tid >> 5;
    fill_tw(tw, tid, 256);

    size_t img = blockIdx.y;
    int row = blockIdx.x * 8 + wrp;
    const float2* ip = Of + (img * HH + row) * (size_t)WB;
    float2* s = rows[wrp];

#pragma unroll
    for (int k = 0; k < 5; k++) {
        int idx = lane + 32 * k;
        if (idx < WB) s[idx] = ip[idx];
    }
    __syncwarp();
#pragma unroll
    for (int k = 0; k < 4; k++) {
        int idx = 129 + lane + 32 * k;
        if (idx < 256) {
            float2 v = s[256 - idx];
            s[idx] = make_float2(v.x, -v.y);   // Hermitian: X[N-k] = conj(X[k])
        }
    }
    __syncthreads();   // tw ready + mirror done

    warp_fft256(s, tw, lane, -1.0f);           // inverse

    float* op = out + (img * HH + row) * (size_t)WW;
    const float scale = 1.0f / 65536.0f;       // 1/(H*W) combined
#pragma unroll
    for (int k = 0; k < 8; k++)
        op[lane + 32 * k] = s[lane + 32 * k].x * scale;
}

// ---------------------------------------------------------------------------
// Launch
// ---------------------------------------------------------------------------
extern "C" void kernel_launch(void* const* d_in, const int* in_sizes, int n_in,
                              void* d_out, int out_size) {
    const float* x = (const float*)d_in[0];     // (16, 32, 256, 256)
    const float* w = (const float*)d_in[1];     // (32, 32, 256, 256)
    float* out = (float*)d_out;                 // (16, 32, 256, 256)

    float2 *xf, *kf, *of;
    cudaGetSymbolAddress((void**)&xf, g_Xf);
    cudaGetSymbolAddress((void**)&kf, g_Kf);
    cudaGetSymbolAddress((void**)&of, g_Of);

    // Forward transforms
    row_fft_kernel<<<dim3(32, NB * NC), 256>>>(x, xf);
    row_fft_kernel<<<dim3(32, NO * NC), 256>>>(w, kf);
    col_fft_kernel<<<dim3(17, NB * NC), 256>>>(xf, 1.0f);
    col_fft_kernel<<<dim3(17, NO * NC), 256>>>(kf, 1.0f);

    // Per-bin channel contraction
    cudaFuncSetAttribute(binconv_kernel,
                         cudaFuncAttributeMaxDynamicSharedMemorySize, 98304);
    binconv_kernel<<<dim3(17, HH), 512, 98304>>>(xf, kf, of);

    // Inverse transforms
    col_fft_kernel<<<dim3(17, NB * NO), 256>>>(of, -1.0f);
    row_irfft_kernel<<<dim3(32, NB * NO), 256>>>(of, out);
}

// round 2
// speedup vs baseline: 3.6806x; 3.6806x over previous
#include <cuda_runtime.h>
#include <math_constants.h>

#define NB 16
#define NC 32
#define NO 32
#define HH 256
#define WW 256
#define WB 129

// Frequency-domain scratch, layout [img][wb][h] (h contiguous)
__device__ float2 g_Xf[(size_t)NB * NC * WB * HH];   // 135 MB
__device__ float2 g_Kf[(size_t)NO * NC * WB * HH];   // 270 MB
__device__ float2 g_Of[(size_t)NB * NO * WB * HH];   // 135 MB

// ---------------------------------------------------------------------------
// complex helpers
// ---------------------------------------------------------------------------
__device__ __forceinline__ float2 cadd(float2 a, float2 b) { return make_float2(a.x + b.x, a.y + b.y); }
__device__ __forceinline__ float2 csub(float2 a, float2 b) { return make_float2(a.x - b.x, a.y - b.y); }
__device__ __forceinline__ float2 cmul(float2 a, float2 b) {
    return make_float2(fmaf(a.x, b.x, -a.y * b.y), fmaf(a.x, b.y, a.y * b.x));
}
template <int DIR>
__device__ __forceinline__ float2 mulJ(float2 a) {   // *(-i) fwd, *(+i) inv
    return (DIR > 0) ? make_float2(a.y, -a.x) : make_float2(-a.y, a.x);
}

// ---------------------------------------------------------------------------
// Register/shuffle FFT-256 per warp. Input: v[j] = x[lane + 32*j] (natural).
// Output: lane holds X[8*bitrev5(lane) + k2] in v[k2].
// DIR=+1 forward (e^{-i}), DIR=-1 inverse (unnormalized).
// ---------------------------------------------------------------------------
template <int DIR>
__device__ __forceinline__ void fft256(float2 v[8], int lane) {
    const float ds = (DIR > 0) ? -1.0f : 1.0f;
    const float S = 0.70710678118654752f;

    // ---- FFT8 over slots (DIT, bit-reversed input indexing) ----
    float2 b0 = cadd(v[0], v[4]), b1 = csub(v[0], v[4]);
    float2 b2 = cadd(v[2], v[6]), b3 = csub(v[2], v[6]);
    float2 b4 = cadd(v[1], v[5]), b5 = csub(v[1], v[5]);
    float2 b6 = cadd(v[3], v[7]), b7 = csub(v[3], v[7]);
    float2 t  = mulJ<DIR>(b3);
    float2 c0 = cadd(b0, b2), c2 = csub(b0, b2);
    float2 c1 = cadd(b1, t),  c3 = csub(b1, t);
    t = mulJ<DIR>(b7);
    float2 c4 = cadd(b4, b6), c6 = csub(b4, b6);
    float2 c5 = cadd(b5, t),  c7 = csub(b5, t);
    const float2 W81 = make_float2(S, ds * S);
    const float2 W83 = make_float2(-S, ds * S);
    v[0] = cadd(c0, c4); v[4] = csub(c0, c4);
    t = cmul(c5, W81);   v[1] = cadd(c1, t); v[5] = csub(c1, t);
    t = mulJ<DIR>(c6);   v[2] = cadd(c2, t); v[6] = csub(c2, t);
    t = cmul(c7, W83);   v[3] = cadd(c3, t); v[7] = csub(c3, t);

    // ---- inter-factor twiddles: v[k2] *= W256^{lane*k2} ----
    float ang = ds * CUDART_PI_F * (float)lane * (1.0f / 128.0f);
    float2 w1; __sincosf(ang, &w1.y, &w1.x);
    float2 w = w1;
    v[1] = cmul(v[1], w);
#pragma unroll
    for (int k = 2; k < 8; k++) { w = cmul(w, w1); v[k] = cmul(v[k], w); }

    // ---- cross-lane FFT32 (DIF) via shfl_xor ----
#pragma unroll
    for (int m = 16; m >= 1; m >>= 1) {
        float2 w2 = make_float2(1.0f, 0.0f);
        if (m > 1) {
            float a2 = ds * CUDART_PI_F * (float)(lane & (m - 1)) / (float)m;
            __sincosf(a2, &w2.y, &w2.x);
        }
        bool up = (lane & m) != 0;
#pragma unroll
        for (int k = 0; k < 8; k++) {
            float2 o;
            o.x = __shfl_xor_sync(0xffffffffu, v[k].x, m);
            o.y = __shfl_xor_sync(0xffffffffu, v[k].y, m);
            v[k] = up ? cmul(csub(o, v[k]), w2) : cadd(v[k], o);
        }
    }
}

// ---------------------------------------------------------------------------
// Pass 1: forward real row FFT, 2 rows packed per complex FFT, output
// transposed to [img][wb][h].  Block: 8 warps = 16 rows; grid (16, nimg).
// ---------------------------------------------------------------------------
__global__ void rowfft_kernel(const float* __restrict__ in,
                              float2* __restrict__ outF) {
    __shared__ float2 zbuf[8][264];   // [pair][k1 + 33*k2]  (conflict-free)
    int tid = threadIdx.x, lane = tid & 31, wrp = tid >> 5;
    size_t img = blockIdx.y;
    int row0 = blockIdx.x * 16;

    const float* pa = in + (img * HH + row0 + 2 * wrp) * (size_t)WW;
    const float* pb = pa + WW;
    float2 v[8];
#pragma unroll
    for (int j = 0; j < 8; j++)
        v[j] = make_float2(pa[lane + 32 * j], pb[lane + 32 * j]);

    fft256<1>(v, lane);

    int k1 = __brev((unsigned)lane) >> 27;
#pragma unroll
    for (int k2 = 0; k2 < 8; k2++) zbuf[wrp][k1 + 33 * k2] = v[k2];
    __syncthreads();

    // unpack packed spectra and write transposed
    for (int idx = tid; idx < WB * 16; idx += 256) {
        int r = idx & 15, k = idx >> 4;
        int p = r >> 1;
        int km = (256 - k) & 255;
        float2 Z  = zbuf[p][(k  & 7) * 33 + (k  >> 3)];
        float2 Zm = zbuf[p][(km & 7) * 33 + (km >> 3)];
        float2 o;
        if (r & 1) o = make_float2(0.5f * (Z.y + Zm.y), 0.5f * (Zm.x - Z.x)); // B
        else       o = make_float2(0.5f * (Z.x + Zm.x), 0.5f * (Z.y - Zm.y)); // A
        outF[(img * WB + k) * (size_t)HH + row0 + r] = o;
    }
}

// ---------------------------------------------------------------------------
// Pass 2/4: column FFT over h, layout [img][wb][h]: pure register FFT,
// fully coalesced, no smem. One warp per (img, wb). In-place.
// ---------------------------------------------------------------------------
template <int DIR>
__global__ void colfft_kernel(float2* __restrict__ F) {
    int gid = blockIdx.x * 8 + (threadIdx.x >> 5);
    int lane = threadIdx.x & 31;
    float2* p = F + (size_t)gid * HH;

    float2 v[8];
#pragma unroll
    for (int j = 0; j < 8; j++) v[j] = p[lane + 32 * j];

    fft256<DIR>(v, lane);

    int base = 8 * (__brev((unsigned)lane) >> 27);
    float4* p4 = (float4*)(p + base);
#pragma unroll
    for (int q = 0; q < 4; q++)
        p4[q] = make_float4(v[2 * q].x, v[2 * q].y, v[2 * q + 1].x, v[2 * q + 1].y);
}

// ---------------------------------------------------------------------------
// Pass 3: per-bin channel contraction.
//   Of[b,o,wb,h] = sum_c Xf[b,c,wb,h] * Kf[o,c,wb,h]
// Block = (h-tile of 8, wb). 512 threads: (b = t>>5, o = t&31).
// ---------------------------------------------------------------------------
__global__ void binconv_kernel(const float2* __restrict__ Xf,
                               const float2* __restrict__ Kf,
                               float2* __restrict__ Of) {
    extern __shared__ float2 sm[];
    float2* Xs = sm;                  // [(c*8+hl)*16 + b]
    float2* Ks = sm + 32 * 8 * 16;    // [(c*8+hl)*32 + o]

    int tid = threadIdx.x;
    int wb = blockIdx.y;
    int h0 = blockIdx.x * 8;
    int hl = tid & 7;
    int sub = tid >> 3;               // 0..63

#pragma unroll
    for (int i = 0; i < 8; i++) {
        int img = i * 64 + sub;       // b*32 + c
        Xs[((img & 31) * 8 + hl) * 16 + (img >> 5)] =
            Xf[((size_t)img * WB + wb) * HH + h0 + hl];
    }
#pragma unroll
    for (int i = 0; i < 16; i++) {
        int img = i * 64 + sub;       // o*32 + c
        Ks[((img & 31) * 8 + hl) * 32 + (img >> 5)] =
            Kf[((size_t)img * WB + wb) * HH + h0 + hl];
    }
    __syncthreads();

    int o = tid & 31, b = tid >> 5;
    float2 acc[8];
#pragma unroll
    for (int q = 0; q < 8; q++) acc[q] = make_float2(0.f, 0.f);

#pragma unroll 4
    for (int c = 0; c < 32; c++) {
#pragma unroll
        for (int q = 0; q < 8; q++) {
            float2 xv = Xs[(c * 8 + q) * 16 + b];   // broadcast
            float2 kv = Ks[(c * 8 + q) * 32 + o];   // conflict-free
            acc[q].x = fmaf(xv.x, kv.x, fmaf(-xv.y, kv.y, acc[q].x));
            acc[q].y = fmaf(xv.x, kv.y, fmaf( xv.y, kv.x, acc[q].y));
        }
    }

    float2* op = Of + (((size_t)(b * NO + o)) * WB + wb) * HH + h0;
#pragma unroll
    for (int q = 0; q < 8; q++) op[q] = acc[q];
}

// ---------------------------------------------------------------------------
// Pass 5: inverse real row FFT (2 rows packed), un-transpose + 1/(H*W) scale.
// Block: 8 warps = 16 rows; grid (16, nimg).
// ---------------------------------------------------------------------------
__global__ void irow_kernel(const float2* __restrict__ OF,
                            float* __restrict__ out) {
    __shared__ float2 sbuf[WB * 17];  // [k][r], pad 17 -> 2-way worst
    int tid = threadIdx.x, lane = tid & 31, wrp = tid >> 5;
    size_t img = blockIdx.y;
    int row0 = blockIdx.x * 16;

    for (int idx = tid; idx < WB * 16; idx += 256) {
        int r = idx & 15, k = idx >> 4;
        sbuf[k * 17 + r] = OF[(img * WB + k) * (size_t)HH + row0 + r];
    }
    __syncthreads();

    // pack rows (2w, 2w+1): Z[k] = A[k] + i*B[k], Hermitian-extend k>128
    float2 v[8];
#pragma unroll
    for (int j = 0; j < 8; j++) {
        int k = lane + 32 * j;
        if (k <= 128) {
            float2 A  = sbuf[k * 17 + 2 * wrp];
            float2 Bv = sbuf[k * 17 + 2 * wrp + 1];
            v[j] = make_float2(A.x - Bv.y, A.y + Bv.x);
        } else {
            int km = 256 - k;
            float2 A  = sbuf[km * 17 + 2 * wrp];
            float2 Bv = sbuf[km * 17 + 2 * wrp + 1];
            v[j] = make_float2(A.x + Bv.y, Bv.x - A.y);
        }
    }

    fft256<-1>(v, lane);

    const float sc = 1.0f / 65536.0f;
    int base = 8 * (__brev((unsigned)lane) >> 27);
    float* oa = out + (img * HH + row0 + 2 * wrp) * (size_t)WW + base;
    float* ob = oa + WW;
    float4* oa4 = (float4*)oa; float4* ob4 = (float4*)ob;
#pragma unroll
    for (int q = 0; q < 2; q++) {
        oa4[q] = make_float4(v[4*q].x * sc, v[4*q+1].x * sc, v[4*q+2].x * sc, v[4*q+3].x * sc);
        ob4[q] = make_float4(v[4*q].y * sc, v[4*q+1].y * sc, v[4*q+2].y * sc, v[4*q+3].y * sc);
    }
}

// ---------------------------------------------------------------------------
// Launch
// ---------------------------------------------------------------------------
extern "C" void kernel_launch(void* const* d_in, const int* in_sizes, int n_in,
                              void* d_out, int out_size) {
    const float* x = (const float*)d_in[0];     // (16, 32, 256, 256)
    const float* w = (const float*)d_in[1];     // (32, 32, 256, 256)
    float* out = (float*)d_out;                 // (16, 32, 256, 256)

    float2 *xf, *kf, *of;
    cudaGetSymbolAddress((void**)&xf, g_Xf);
    cudaGetSymbolAddress((void**)&kf, g_Kf);
    cudaGetSymbolAddress((void**)&of, g_Of);

    // Pass 1: row rFFT (packed pairs) + transpose
    rowfft_kernel<<<dim3(16, NB * NC), 256>>>(x, xf);
    rowfft_kernel<<<dim3(16, NO * NC), 256>>>(w, kf);

    // Pass 2: column FFT (register/shuffle, coalesced)
    colfft_kernel<1><<<(NB * NC * WB) / 8, 256>>>(xf);
    colfft_kernel<1><<<(NO * NC * WB) / 8, 256>>>(kf);

    // Pass 3: per-bin channel contraction
    cudaFuncSetAttribute(binconv_kernel,
                         cudaFuncAttributeMaxDynamicSharedMemorySize, 98304);
    binconv_kernel<<<dim3(32, WB), 512, 98304>>>(xf, kf, of);

    // Pass 4: inverse column FFT
    colfft_kernel<-1><<<(NB * NO * WB) / 8, 256>>>(of);

    // Pass 5: inverse row FFT (packed) + un-transpose + scale
    irow_kernel<<<dim3(16, NB * NO), 256>>>(of, out);
}

// round 3
// speedup vs baseline: 6.0891x; 1.6544x over previous
#include <cuda_runtime.h>
#include <math_constants.h>

#define NB 16
#define NC 32
#define NO 32
#define HH 256
#define WW 256
#define WB 129

// Frequency-domain scratch, layout [img][wb][h] (h contiguous)
__device__ float2 g_Xf[(size_t)NB * NC * WB * HH];
__device__ float2 g_Kf[(size_t)NO * NC * WB * HH];
__device__ float2 g_Of[(size_t)NB * NO * WB * HH];

__device__ __forceinline__ float2 cadd(float2 a, float2 b) { return make_float2(a.x + b.x, a.y + b.y); }
__device__ __forceinline__ float2 csub(float2 a, float2 b) { return make_float2(a.x - b.x, a.y - b.y); }
__device__ __forceinline__ float2 cmul(float2 a, float2 b) {
    return make_float2(fmaf(a.x, b.x, -a.y * b.y), fmaf(a.x, b.y, a.y * b.x));
}
template <int DIR>
__device__ __forceinline__ float2 mulJ(float2 a) {
    return (DIR > 0) ? make_float2(a.y, -a.x) : make_float2(-a.y, a.x);
}

// ---------------------------------------------------------------------------
// Register/shuffle FFT-256 per warp. Input: v[j] = x[lane + 32*j] (natural).
// Output: lane holds X[8*bitrev5(lane) + k2] in v[k2].
// ---------------------------------------------------------------------------
template <int DIR>
__device__ __forceinline__ void fft256(float2 v[8], int lane) {
    const float ds = (DIR > 0) ? -1.0f : 1.0f;
    const float S = 0.70710678118654752f;

    // ---- FFT8 over slots (DIT, bit-reversed input indexing) ----
    float2 b0 = cadd(v[0], v[4]), b1 = csub(v[0], v[4]);
    float2 b2 = cadd(v[2], v[6]), b3 = csub(v[2], v[6]);
    float2 b4 = cadd(v[1], v[5]), b5 = csub(v[1], v[5]);
    float2 b6 = cadd(v[3], v[7]), b7 = csub(v[3], v[7]);
    float2 t  = mulJ<DIR>(b3);
    float2 c0 = cadd(b0, b2), c2 = csub(b0, b2);
    float2 c1 = cadd(b1, t),  c3 = csub(b1, t);
    t = mulJ<DIR>(b7);
    float2 c4 = cadd(b4, b6), c6 = csub(b4, b6);
    float2 c5 = cadd(b5, t),  c7 = csub(b5, t);
    const float2 W81 = make_float2(S, ds * S);
    const float2 W83 = make_float2(-S, ds * S);
    v[0] = cadd(c0, c4); v[4] = csub(c0, c4);
    t = cmul(c5, W81);   v[1] = cadd(c1, t); v[5] = csub(c1, t);
    t = mulJ<DIR>(c6);   v[2] = cadd(c2, t); v[6] = csub(c2, t);
    t = cmul(c7, W83);   v[3] = cadd(c3, t); v[7] = csub(c3, t);

    // ---- inter-factor twiddles via tree (shallow dep chain) ----
    float ang = ds * CUDART_PI_F * (float)lane * (1.0f / 128.0f);
    float2 w1; __sincosf(ang, &w1.y, &w1.x);
    float2 w2 = cmul(w1, w1);
    float2 w3 = cmul(w2, w1);
    float2 w4 = cmul(w2, w2);
    float2 w5 = cmul(w4, w1);
    float2 w6 = cmul(w3, w3);
    float2 w7 = cmul(w4, w3);
    v[1] = cmul(v[1], w1); v[2] = cmul(v[2], w2); v[3] = cmul(v[3], w3);
    v[4] = cmul(v[4], w4); v[5] = cmul(v[5], w5); v[6] = cmul(v[6], w6);
    v[7] = cmul(v[7], w7);

    // ---- cross-lane FFT32 (DIF) via shfl_xor; hoisted per-stage s/wEff ----
#pragma unroll
    for (int m = 16; m >= 1; m >>= 1) {
        bool up = (lane & m) != 0;
        float s = up ? -1.0f : 1.0f;
        float2 wo;
        if (m > 1) {
            float a2 = ds * CUDART_PI_F * (float)(lane & (m - 1)) / (float)m;
            float2 w; __sincosf(a2, &w.y, &w.x);
            wo = up ? w : make_float2(1.0f, 0.0f);
        }
#pragma unroll
        for (int k = 0; k < 8; k++) {
            float ox = __shfl_xor_sync(0xffffffffu, v[k].x, m);
            float oy = __shfl_xor_sync(0xffffffffu, v[k].y, m);
            float tx = fmaf(s, v[k].x, ox);     // down: v+o ; up: o-v
            float ty = fmaf(s, v[k].y, oy);
            if (m > 1) v[k] = cmul(make_float2(tx, ty), wo);
            else       v[k] = make_float2(tx, ty);
        }
    }
}

// ---------------------------------------------------------------------------
// Pass 1: forward real row FFT, 2 rows packed, output transposed [img][wb][h]
// ---------------------------------------------------------------------------
__global__ void __launch_bounds__(256, 4)
rowfft_kernel(const float* __restrict__ in, float2* __restrict__ outF) {
    __shared__ float2 zbuf[8][264];
    int tid = threadIdx.x, lane = tid & 31, wrp = tid >> 5;
    size_t img = blockIdx.y;
    int row0 = blockIdx.x * 16;

    const float* pa = in + (img * HH + row0 + 2 * wrp) * (size_t)WW;
    const float* pb = pa + WW;
    float2 v[8];
#pragma unroll
    for (int j = 0; j < 8; j++)
        v[j] = make_float2(pa[lane + 32 * j], pb[lane + 32 * j]);

    fft256<1>(v, lane);

    int k1 = __brev((unsigned)lane) >> 27;
#pragma unroll
    for (int k2 = 0; k2 < 8; k2++) zbuf[wrp][k1 + 33 * k2] = v[k2];
    __syncthreads();

    for (int idx = tid; idx < WB * 16; idx += 256) {
        int r = idx & 15, k = idx >> 4;
        int p = r >> 1;
        int km = (256 - k) & 255;
        float2 Z  = zbuf[p][(k  & 7) * 33 + (k  >> 3)];
        float2 Zm = zbuf[p][(km & 7) * 33 + (km >> 3)];
        float2 o;
        if (r & 1) o = make_float2(0.5f * (Z.y + Zm.y), 0.5f * (Zm.x - Z.x));
        else       o = make_float2(0.5f * (Z.x + Zm.x), 0.5f * (Z.y - Zm.y));
        outF[(img * WB + k) * (size_t)HH + row0 + r] = o;
    }
}

// ---------------------------------------------------------------------------
// Pass 2/4: column FFT over h, contiguous, register-only. In-place.
// ---------------------------------------------------------------------------
template <int DIR>
__global__ void __launch_bounds__(256, 4)
colfft_kernel(float2* __restrict__ F) {
    int gid = blockIdx.x * 8 + (threadIdx.x >> 5);
    int lane = threadIdx.x & 31;
    float2* p = F + (size_t)gid * HH;

    float2 v[8];
#pragma unroll
    for (int j = 0; j < 8; j++) v[j] = p[lane + 32 * j];

    fft256<DIR>(v, lane);

    int base = 8 * (__brev((unsigned)lane) >> 27);
    float4* p4 = (float4*)(p + base);
#pragma unroll
    for (int q = 0; q < 4; q++)
        p4[q] = make_float4(v[2 * q].x, v[2 * q].y, v[2 * q + 1].x, v[2 * q + 1].y);
}

// ---------------------------------------------------------------------------
// Pass 3: per-bin channel contraction with 4b x 2o register tiling.
//   Of[b,o,wb,h] = sum_c Xf[b,c,wb,h] * Kf[o,c,wb,h]
// Block = (h-tile of 8, wb). 512 threads: tid = op*32 + q*4 + bq.
// smem (padded float4 strides 9 / 17 for conflict-free LDS.128):
//   Xs: [(c*8+q)*18 + b]  (float2 units, 36864 B)
//   Ks: [(c*8+q)*34 + o]  (float2 units, 69632 B)
// ---------------------------------------------------------------------------
#define XSTR 18
#define KSTR 34
__global__ void __launch_bounds__(512, 2)
binconv_kernel(const float2* __restrict__ Xf, const float2* __restrict__ Kf,
               float2* __restrict__ Of) {
    extern __shared__ float2 sm[];
    float2* Xs = sm;                      // 32*8*XSTR float2
    float2* Ks = sm + 32 * 8 * XSTR;      // 32*8*KSTR float2

    int tid = threadIdx.x;
    int wb = blockIdx.y;
    int h0 = blockIdx.x * 8;
    int hl = tid & 7;
    int sub = tid >> 3;

#pragma unroll
    for (int i = 0; i < 8; i++) {
        int img = i * 64 + sub;           // b*32 + c
        Xs[((img & 31) * 8 + hl) * XSTR + (img >> 5)] =
            Xf[((size_t)img * WB + wb) * HH + h0 + hl];
    }
#pragma unroll
    for (int i = 0; i < 16; i++) {
        int img = i * 64 + sub;           // o*32 + c
        Ks[((img & 31) * 8 + hl) * KSTR + (img >> 5)] =
            Kf[((size_t)img * WB + wb) * HH + h0 + hl];
    }
    __syncthreads();

    int bq = tid & 3;                     // b0 = 4*bq
    int q  = (tid >> 2) & 7;              // h = h0 + q
    int op = tid >> 5;                    // o0 = 2*op
    const float4* X4 = (const float4*)Xs;
    const float4* K4 = (const float4*)Ks;

    float2 acc[4][2];
#pragma unroll
    for (int bi = 0; bi < 4; bi++)
#pragma unroll
        for (int oi = 0; oi < 2; oi++) acc[bi][oi] = make_float2(0.f, 0.f);

#pragma unroll 4
    for (int c = 0; c < 32; c++) {
        int xrow = (c * 8 + q) * (XSTR / 2);
        int krow = (c * 8 + q) * (KSTR / 2);
        float4 xa = X4[xrow + 2 * bq];
        float4 xb = X4[xrow + 2 * bq + 1];
        float4 kv = K4[krow + op];
        float xr[4] = {xa.x, xa.z, xb.x, xb.z};
        float xi[4] = {xa.y, xa.w, xb.y, xb.w};
        float kr[2] = {kv.x, kv.z};
        float ki[2] = {kv.y, kv.w};
#pragma unroll
        for (int bi = 0; bi < 4; bi++)
#pragma unroll
            for (int oi = 0; oi < 2; oi++) {
                acc[bi][oi].x = fmaf(xr[bi], kr[oi], fmaf(-xi[bi], ki[oi], acc[bi][oi].x));
                acc[bi][oi].y = fmaf(xr[bi], ki[oi], fmaf( xi[bi], kr[oi], acc[bi][oi].y));
            }
    }

    int b0 = 4 * bq, o0 = 2 * op, h = h0 + q;
#pragma unroll
    for (int bi = 0; bi < 4; bi++)
#pragma unroll
        for (int oi = 0; oi < 2; oi++)
            Of[(((size_t)(b0 + bi) * NO + o0 + oi) * WB + wb) * HH + h] = acc[bi][oi];
}

// ---------------------------------------------------------------------------
// Pass 5: inverse real row FFT (2 rows packed), un-transpose + 1/(H*W) scale.
// ---------------------------------------------------------------------------
__global__ void __launch_bounds__(256, 4)
irow_kernel(const float2* __restrict__ OF, float* __restrict__ out) {
    __shared__ float2 sbuf[WB * 17];
    int tid = threadIdx.x, lane = tid & 31, wrp = tid >> 5;
    size_t img = blockIdx.y;
    int row0 = blockIdx.x * 16;

    for (int idx = tid; idx < WB * 16; idx += 256) {
        int r = idx & 15, k = idx >> 4;
        sbuf[k * 17 + r] = OF[(img * WB + k) * (size_t)HH + row0 + r];
    }
    __syncthreads();

    float2 v[8];
#pragma unroll
    for (int j = 0; j < 8; j++) {
        int k = lane + 32 * j;
        if (k <= 128) {
            float2 A  = sbuf[k * 17 + 2 * wrp];
            float2 Bv = sbuf[k * 17 + 2 * wrp + 1];
            v[j] = make_float2(A.x - Bv.y, A.y + Bv.x);
        } else {
            int km = 256 - k;
            float2 A  = sbuf[km * 17 + 2 * wrp];
            float2 Bv = sbuf[km * 17 + 2 * wrp + 1];
            v[j] = make_float2(A.x + Bv.y, Bv.x - A.y);
        }
    }

    fft256<-1>(v, lane);

    const float sc = 1.0f / 65536.0f;
    int base = 8 * (__brev((unsigned)lane) >> 27);
    float* oa = out + (img * HH + row0 + 2 * wrp) * (size_t)WW + base;
    float* ob = oa + WW;
    float4* oa4 = (float4*)oa; float4* ob4 = (float4*)ob;
#pragma unroll
    for (int qq = 0; qq < 2; qq++) {
        oa4[qq] = make_float4(v[4*qq].x * sc, v[4*qq+1].x * sc, v[4*qq+2].x * sc, v[4*qq+3].x * sc);
        ob4[qq] = make_float4(v[4*qq].y * sc, v[4*qq+1].y * sc, v[4*qq+2].y * sc, v[4*qq+3].y * sc);
    }
}

// ---------------------------------------------------------------------------
extern "C" void kernel_launch(void* const* d_in, const int* in_sizes, int n_in,
                              void* d_out, int out_size) {
    const float* x = (const float*)d_in[0];
    const float* w = (const float*)d_in[1];
    float* out = (float*)d_out;

    float2 *xf, *kf, *of;
    cudaGetSymbolAddress((void**)&xf, g_Xf);
    cudaGetSymbolAddress((void**)&kf, g_Kf);
    cudaGetSymbolAddress((void**)&of, g_Of);

    rowfft_kernel<<<dim3(16, NB * NC), 256>>>(x, xf);
    rowfft_kernel<<<dim3(16, NO * NC), 256>>>(w, kf);

    colfft_kernel<1><<<(NB * NC * WB) / 8, 256>>>(xf);
    colfft_kernel<1><<<(NO * NC * WB) / 8, 256>>>(kf);

    size_t bsm = (size_t)(32 * 8 * (XSTR + KSTR)) * sizeof(float2);  // 106496
    cudaFuncSetAttribute(binconv_kernel,
                         cudaFuncAttributeMaxDynamicSharedMemorySize, (int)bsm);
    binconv_kernel<<<dim3(32, WB), 512, bsm>>>(xf, kf, of);

    colfft_kernel<-1><<<(NB * NO * WB) / 8, 256>>>(of);

    irow_kernel<<<dim3(16, NB * NO), 256>>>(of, out);
}

// round 4
// speedup vs baseline: 7.0241x; 1.1536x over previous
#include <cuda_runtime.h>
#include <math_constants.h>

#define NB 16
#define NC 32
#define NO 32
#define HH 256
#define WW 256
#define WB 129

// Frequency-domain scratch, layout [img][wb][h]; h is PERMUTED between the
// forward and inverse column FFTs (position k2*32+lane <-> freq 8*br5(lane)+k2)
__device__ float2 g_Xf[(size_t)NB * NC * WB * HH];
__device__ float2 g_Kf[(size_t)NO * NC * WB * HH];
__device__ float2 g_Of[(size_t)NB * NO * WB * HH];

__device__ __forceinline__ float2 cadd(float2 a, float2 b) { return make_float2(a.x + b.x, a.y + b.y); }
__device__ __forceinline__ float2 csub(float2 a, float2 b) { return make_float2(a.x - b.x, a.y - b.y); }
__device__ __forceinline__ float2 cmul(float2 a, float2 b) {
    return make_float2(fmaf(a.x, b.x, -a.y * b.y), fmaf(a.x, b.y, a.y * b.x));
}
template <int DIR>
__device__ __forceinline__ float2 mulJ(float2 a) {
    return (DIR > 0) ? make_float2(a.y, -a.x) : make_float2(-a.y, a.x);
}

// FFT8 over register slots (natural in / natural out), e^{-i} for DIR=+1
template <int DIR>
__device__ __forceinline__ void fft8_slots(float2 v[8]) {
    const float ds = (DIR > 0) ? -1.0f : 1.0f;
    const float S = 0.70710678118654752f;
    float2 b0 = cadd(v[0], v[4]), b1 = csub(v[0], v[4]);
    float2 b2 = cadd(v[2], v[6]), b3 = csub(v[2], v[6]);
    float2 b4 = cadd(v[1], v[5]), b5 = csub(v[1], v[5]);
    float2 b6 = cadd(v[3], v[7]), b7 = csub(v[3], v[7]);
    float2 t  = mulJ<DIR>(b3);
    float2 c0 = cadd(b0, b2), c2 = csub(b0, b2);
    float2 c1 = cadd(b1, t),  c3 = csub(b1, t);
    t = mulJ<DIR>(b7);
    float2 c4 = cadd(b4, b6), c6 = csub(b4, b6);
    float2 c5 = cadd(b5, t),  c7 = csub(b5, t);
    const float2 W81 = make_float2(S, ds * S);
    const float2 W83 = make_float2(-S, ds * S);
    v[0] = cadd(c0, c4); v[4] = csub(c0, c4);
    t = cmul(c5, W81);   v[1] = cadd(c1, t); v[5] = csub(c1, t);
    t = mulJ<DIR>(c6);   v[2] = cadd(c2, t); v[6] = csub(c2, t);
    t = cmul(c7, W83);   v[3] = cadd(c3, t); v[7] = csub(c3, t);
}

// ---------------------------------------------------------------------------
// Forward register/shuffle FFT-256. Input v[j] = x[lane+32*j] (natural).
// Output: lane holds X[8*br5(lane)+k2] in v[k2].
// ---------------------------------------------------------------------------
template <int DIR>
__device__ __forceinline__ void fft256(float2 v[8], int lane) {
    const float ds = (DIR > 0) ? -1.0f : 1.0f;
    fft8_slots<DIR>(v);

    float ang = ds * CUDART_PI_F * (float)lane * (1.0f / 128.0f);
    float2 w1; __sincosf(ang, &w1.y, &w1.x);
    float2 w2 = cmul(w1, w1);
    float2 w3 = cmul(w2, w1);
    float2 w4 = cmul(w2, w2);
    float2 w5 = cmul(w4, w1);
    float2 w6 = cmul(w3, w3);
    float2 w7 = cmul(w4, w3);
    v[1] = cmul(v[1], w1); v[2] = cmul(v[2], w2); v[3] = cmul(v[3], w3);
    v[4] = cmul(v[4], w4); v[5] = cmul(v[5], w5); v[6] = cmul(v[6], w6);
    v[7] = cmul(v[7], w7);

#pragma unroll
    for (int m = 16; m >= 1; m >>= 1) {
        bool up = (lane & m) != 0;
        float s = up ? -1.0f : 1.0f;
        float2 wo;
        if (m > 1) {
            float a2 = ds * CUDART_PI_F * (float)(lane & (m - 1)) / (float)m;
            float2 w; __sincosf(a2, &w.y, &w.x);
            wo = up ? w : make_float2(1.0f, 0.0f);
        }
#pragma unroll
        for (int k = 0; k < 8; k++) {
            float ox = __shfl_xor_sync(0xffffffffu, v[k].x, m);
            float oy = __shfl_xor_sync(0xffffffffu, v[k].y, m);
            float tx = fmaf(s, v[k].x, ox);
            float ty = fmaf(s, v[k].y, oy);
            if (m > 1) v[k] = cmul(make_float2(tx, ty), wo);
            else       v[k] = make_float2(tx, ty);
        }
    }
}

// ---------------------------------------------------------------------------
// Adjoint (unnormalized inverse) of fft256<1>. Input: lane holds
// X[8*br5(lane)+k2] in v[k2] (forward output order). Output: natural
// v[j] = 256 * x[lane+32*j].
// ---------------------------------------------------------------------------
__device__ __forceinline__ void ifft256_adj(float2 v[8], int lane) {
#pragma unroll
    for (int m = 1; m <= 16; m <<= 1) {
        bool up = (lane & m) != 0;
        if (m > 1) {
            float a2 = CUDART_PI_F * (float)(lane & (m - 1)) / (float)m; // conj
            float2 w; __sincosf(a2, &w.y, &w.x);
            float2 wo = up ? w : make_float2(1.0f, 0.0f);
#pragma unroll
            for (int k = 0; k < 8; k++) v[k] = cmul(v[k], wo);
        }
        float s = up ? -1.0f : 1.0f;
#pragma unroll
        for (int k = 0; k < 8; k++) {
            float ox = __shfl_xor_sync(0xffffffffu, v[k].x, m);
            float oy = __shfl_xor_sync(0xffffffffu, v[k].y, m);
            v[k].x = fmaf(s, v[k].x, ox);
            v[k].y = fmaf(s, v[k].y, oy);
        }
    }
    // conj inter-factor twiddles
    float ang = CUDART_PI_F * (float)lane * (1.0f / 128.0f);
    float2 w1; __sincosf(ang, &w1.y, &w1.x);
    float2 w2 = cmul(w1, w1);
    float2 w3 = cmul(w2, w1);
    float2 w4 = cmul(w2, w2);
    float2 w5 = cmul(w4, w1);
    float2 w6 = cmul(w3, w3);
    float2 w7 = cmul(w4, w3);
    v[1] = cmul(v[1], w1); v[2] = cmul(v[2], w2); v[3] = cmul(v[3], w3);
    v[4] = cmul(v[4], w4); v[5] = cmul(v[5], w5); v[6] = cmul(v[6], w6);
    v[7] = cmul(v[7], w7);

    fft8_slots<-1>(v);
}

// ---------------------------------------------------------------------------
// Pass 1: forward real row FFT, 2 rows packed, output transposed [img][wb][h]
// ---------------------------------------------------------------------------
__global__ void __launch_bounds__(256)
rowfft_kernel(const float* __restrict__ in, float2* __restrict__ outF) {
    __shared__ float2 zbuf[8][264];
    int tid = threadIdx.x, lane = tid & 31, wrp = tid >> 5;
    size_t img = blockIdx.y;
    int row0 = blockIdx.x * 16;

    const float* pa = in + (img * HH + row0 + 2 * wrp) * (size_t)WW;
    const float* pb = pa + WW;
    float2 v[8];
#pragma unroll
    for (int j = 0; j < 8; j++)
        v[j] = make_float2(pa[lane + 32 * j], pb[lane + 32 * j]);

    fft256<1>(v, lane);

    int k1 = __brev((unsigned)lane) >> 27;
#pragma unroll
    for (int k2 = 0; k2 < 8; k2++) zbuf[wrp][k1 + 33 * k2] = v[k2];
    __syncthreads();

    for (int idx = tid; idx < WB * 16; idx += 256) {
        int r = idx & 15, k = idx >> 4;
        int p = r >> 1;
        int km = (256 - k) & 255;
        float2 Z  = zbuf[p][(k  & 7) * 33 + (k  >> 3)];
        float2 Zm = zbuf[p][(km & 7) * 33 + (km >> 3)];
        float2 o;
        if (r & 1) o = make_float2(0.5f * (Z.y + Zm.y), 0.5f * (Zm.x - Z.x));
        else       o = make_float2(0.5f * (Z.x + Zm.x), 0.5f * (Z.y - Zm.y));
        outF[(img * WB + k) * (size_t)HH + row0 + r] = o;
    }
}

// ---------------------------------------------------------------------------
// Pass 2: forward column FFT over h. Coalesced loads (natural h) and stores
// (permuted h: position k2*32+lane). In-place.
// ---------------------------------------------------------------------------
__global__ void __launch_bounds__(512)
colfft_fwd_kernel(float2* __restrict__ F) {
    int gid = blockIdx.x * 16 + (threadIdx.x >> 5);
    int lane = threadIdx.x & 31;
    float2* p = F + (size_t)gid * HH;

    float2 v[8];
#pragma unroll
    for (int j = 0; j < 8; j++) v[j] = p[lane + 32 * j];

    fft256<1>(v, lane);

#pragma unroll
    for (int k2 = 0; k2 < 8; k2++) p[k2 * 32 + lane] = v[k2];  // coalesced
}

// ---------------------------------------------------------------------------
// Pass 4: inverse column FFT over h. Loads permuted order (coalesced),
// adjoint network, stores natural h (coalesced). In-place.
// ---------------------------------------------------------------------------
__global__ void __launch_bounds__(512)
colfft_inv_kernel(float2* __restrict__ F) {
    int gid = blockIdx.x * 16 + (threadIdx.x >> 5);
    int lane = threadIdx.x & 31;
    float2* p = F + (size_t)gid * HH;

    float2 v[8];
#pragma unroll
    for (int k2 = 0; k2 < 8; k2++) v[k2] = p[k2 * 32 + lane];

    ifft256_adj(v, lane);

#pragma unroll
    for (int j = 0; j < 8; j++) p[lane + 32 * j] = v[j];       // coalesced
}

// ---------------------------------------------------------------------------
// Pass 3: per-bin channel contraction with 4b x 2o register tiling.
// (h here is the permuted index; pointwise, so consistent across X/K/O.)
// ---------------------------------------------------------------------------
#define XSTR 18
#define KSTR 34
__global__ void __launch_bounds__(512, 2)
binconv_kernel(const float2* __restrict__ Xf, const float2* __restrict__ Kf,
               float2* __restrict__ Of) {
    extern __shared__ float2 sm[];
    float2* Xs = sm;
    float2* Ks = sm + 32 * 8 * XSTR;

    int tid = threadIdx.x;
    int wb = blockIdx.y;
    int h0 = blockIdx.x * 8;
    int hl = tid & 7;
    int sub = tid >> 3;

#pragma unroll
    for (int i = 0; i < 8; i++) {
        int img = i * 64 + sub;           // b*32 + c
        Xs[((img & 31) * 8 + hl) * XSTR + (img >> 5)] =
            Xf[((size_t)img * WB + wb) * HH + h0 + hl];
    }
#pragma unroll
    for (int i = 0; i < 16; i++) {
        int img = i * 64 + sub;           // o*32 + c
        Ks[((img & 31) * 8 + hl) * KSTR + (img >> 5)] =
            Kf[((size_t)img * WB + wb) * HH + h0 + hl];
    }
    __syncthreads();

    int bq = tid & 3;
    int q  = (tid >> 2) & 7;
    int op = tid >> 5;
    const float4* X4 = (const float4*)Xs;
    const float4* K4 = (const float4*)Ks;

    float2 acc[4][2];
#pragma unroll
    for (int bi = 0; bi < 4; bi++)
#pragma unroll
        for (int oi = 0; oi < 2; oi++) acc[bi][oi] = make_float2(0.f, 0.f);

#pragma unroll 4
    for (int c = 0; c < 32; c++) {
        int xrow = (c * 8 + q) * (XSTR / 2);
        int krow = (c * 8 + q) * (KSTR / 2);
        float4 xa = X4[xrow + 2 * bq];
        float4 xb = X4[xrow + 2 * bq + 1];
        float4 kv = K4[krow + op];
        float xr[4] = {xa.x, xa.z, xb.x, xb.z};
        float xi[4] = {xa.y, xa.w, xb.y, xb.w};
        float kr[2] = {kv.x, kv.z};
        float ki[2] = {kv.y, kv.w};
#pragma unroll
        for (int bi = 0; bi < 4; bi++)
#pragma unroll
            for (int oi = 0; oi < 2; oi++) {
                acc[bi][oi].x = fmaf(xr[bi], kr[oi], fmaf(-xi[bi], ki[oi], acc[bi][oi].x));
                acc[bi][oi].y = fmaf(xr[bi], ki[oi], fmaf( xi[bi], kr[oi], acc[bi][oi].y));
            }
    }

    int b0 = 4 * bq, o0 = 2 * op, h = h0 + q;
#pragma unroll
    for (int bi = 0; bi < 4; bi++)
#pragma unroll
        for (int oi = 0; oi < 2; oi++)
            Of[(((size_t)(b0 + bi) * NO + o0 + oi) * WB + wb) * HH + h] = acc[bi][oi];
}

// ---------------------------------------------------------------------------
// Pass 5: inverse real row FFT (2 rows packed), un-transpose + 1/(H*W) scale.
// ---------------------------------------------------------------------------
__global__ void __launch_bounds__(256)
irow_kernel(const float2* __restrict__ OF, float* __restrict__ out) {
    __shared__ float2 sbuf[WB * 17];
    int tid = threadIdx.x, lane = tid & 31, wrp = tid >> 5;
    size_t img = blockIdx.y;
    int row0 = blockIdx.x * 16;

    for (int idx = tid; idx < WB * 16; idx += 256) {
        int r = idx & 15, k = idx >> 4;
        sbuf[k * 17 + r] = OF[(img * WB + k) * (size_t)HH + row0 + r];
    }
    __syncthreads();

    float2 v[8];
#pragma unroll
    for (int j = 0; j < 8; j++) {
        int k = lane + 32 * j;
        if (k <= 128) {
            float2 A  = sbuf[k * 17 + 2 * wrp];
            float2 Bv = sbuf[k * 17 + 2 * wrp + 1];
            v[j] = make_float2(A.x - Bv.y, A.y + Bv.x);
        } else {
            int km = 256 - k;
            float2 A  = sbuf[km * 17 + 2 * wrp];
            float2 Bv = sbuf[km * 17 + 2 * wrp + 1];
            v[j] = make_float2(A.x + Bv.y, Bv.x - A.y);
        }
    }

    fft256<-1>(v, lane);

    const float sc = 1.0f / 65536.0f;
    int base = 8 * (__brev((unsigned)lane) >> 27);
    float* oa = out + (img * HH + row0 + 2 * wrp) * (size_t)WW + base;
    float* ob = oa + WW;
    float4* oa4 = (float4*)oa; float4* ob4 = (float4*)ob;
#pragma unroll
    for (int qq = 0; qq < 2; qq++) {
        oa4[qq] = make_float4(v[4*qq].x * sc, v[4*qq+1].x * sc, v[4*qq+2].x * sc, v[4*qq+3].x * sc);
        ob4[qq] = make_float4(v[4*qq].y * sc, v[4*qq+1].y * sc, v[4*qq+2].y * sc, v[4*qq+3].y * sc);
    }
}

// ---------------------------------------------------------------------------
extern "C" void kernel_launch(void* const* d_in, const int* in_sizes, int n_in,
                              void* d_out, int out_size) {
    const float* x = (const float*)d_in[0];
    const float* w = (const float*)d_in[1];
    float* out = (float*)d_out;

    float2 *xf, *kf, *of;
    cudaGetSymbolAddress((void**)&xf, g_Xf);
    cudaGetSymbolAddress((void**)&kf, g_Kf);
    cudaGetSymbolAddress((void**)&of, g_Of);

    rowfft_kernel<<<dim3(16, NB * NC), 256>>>(x, xf);
    rowfft_kernel<<<dim3(16, NO * NC), 256>>>(w, kf);

    colfft_fwd_kernel<<<(NB * NC * WB + 15) / 16, 512>>>(xf);
    colfft_fwd_kernel<<<(NO * NC * WB + 15) / 16, 512>>>(kf);

    size_t bsm = (size_t)(32 * 8 * (XSTR + KSTR)) * sizeof(float2);
    cudaFuncSetAttribute(binconv_kernel,
                         cudaFuncAttributeMaxDynamicSharedMemorySize, (int)bsm);
    binconv_kernel<<<dim3(32, WB), 512, bsm>>>(xf, kf, of);

    colfft_inv_kernel<<<(NB * NO * WB + 15) / 16, 512>>>(of);

    irow_kernel<<<dim3(16, NB * NO), 256>>>(of, out);
}

// round 5
// speedup vs baseline: 7.7881x; 1.1088x over previous
#include <cuda_runtime.h>
#include <cuda_fp16.h>
#include <math_constants.h>

#define NB 16
#define NC 32
#define NO 32
#define HH 256
#define WW 256
#define WB 129

// Frequency-domain scratch in fp16 (half2 = one complex), layout [img][wb][h];
// h is PERMUTED between forward and inverse column FFTs.
__device__ __half2 g_Xf[(size_t)NB * NC * WB * HH];   // 67.6 MB
__device__ __half2 g_Kf[(size_t)NO * NC * WB * HH];   // 135 MB
__device__ __half2 g_Of[(size_t)NB * NO * WB * HH];   // 67.6 MB

__device__ __forceinline__ float2 cadd(float2 a, float2 b) { return make_float2(a.x + b.x, a.y + b.y); }
__device__ __forceinline__ float2 csub(float2 a, float2 b) { return make_float2(a.x - b.x, a.y - b.y); }
__device__ __forceinline__ float2 cmul(float2 a, float2 b) {
    return make_float2(fmaf(a.x, b.x, -a.y * b.y), fmaf(a.x, b.y, a.y * b.x));
}
template <int DIR>
__device__ __forceinline__ float2 mulJ(float2 a) {
    return (DIR > 0) ? make_float2(a.y, -a.x) : make_float2(-a.y, a.x);
}
__device__ __forceinline__ float2 h2f(__half2 h) { return __half22float2(h); }
__device__ __forceinline__ __half2 f2h(float2 f) { return __floats2half2_rn(f.x, f.y); }

// FFT8 over register slots (natural in / natural out), e^{-i} for DIR=+1
template <int DIR>
__device__ __forceinline__ void fft8_slots(float2 v[8]) {
    const float ds = (DIR > 0) ? -1.0f : 1.0f;
    const float S = 0.70710678118654752f;
    float2 b0 = cadd(v[0], v[4]), b1 = csub(v[0], v[4]);
    float2 b2 = cadd(v[2], v[6]), b3 = csub(v[2], v[6]);
    float2 b4 = cadd(v[1], v[5]), b5 = csub(v[1], v[5]);
    float2 b6 = cadd(v[3], v[7]), b7 = csub(v[3], v[7]);
    float2 t  = mulJ<DIR>(b3);
    float2 c0 = cadd(b0, b2), c2 = csub(b0, b2);
    float2 c1 = cadd(b1, t),  c3 = csub(b1, t);
    t = mulJ<DIR>(b7);
    float2 c4 = cadd(b4, b6), c6 = csub(b4, b6);
    float2 c5 = cadd(b5, t),  c7 = csub(b5, t);
    const float2 W81 = make_float2(S, ds * S);
    const float2 W83 = make_float2(-S, ds * S);
    v[0] = cadd(c0, c4); v[4] = csub(c0, c4);
    t = cmul(c5, W81);   v[1] = cadd(c1, t); v[5] = csub(c1, t);
    t = mulJ<DIR>(c6);   v[2] = cadd(c2, t); v[6] = csub(c2, t);
    t = cmul(c7, W83);   v[3] = cadd(c3, t); v[7] = csub(c3, t);
}

// Forward register/shuffle FFT-256. Input v[j]=x[lane+32*j]. Output: lane
// holds X[8*br5(lane)+k2] in v[k2].
template <int DIR>
__device__ __forceinline__ void fft256(float2 v[8], int lane) {
    const float ds = (DIR > 0) ? -1.0f : 1.0f;
    fft8_slots<DIR>(v);

    float ang = ds * CUDART_PI_F * (float)lane * (1.0f / 128.0f);
    float2 w1; __sincosf(ang, &w1.y, &w1.x);
    float2 w2 = cmul(w1, w1);
    float2 w3 = cmul(w2, w1);
    float2 w4 = cmul(w2, w2);
    float2 w5 = cmul(w4, w1);
    float2 w6 = cmul(w3, w3);
    float2 w7 = cmul(w4, w3);
    v[1] = cmul(v[1], w1); v[2] = cmul(v[2], w2); v[3] = cmul(v[3], w3);
    v[4] = cmul(v[4], w4); v[5] = cmul(v[5], w5); v[6] = cmul(v[6], w6);
    v[7] = cmul(v[7], w7);

#pragma unroll
    for (int m = 16; m >= 1; m >>= 1) {
        bool up = (lane & m) != 0;
        float s = up ? -1.0f : 1.0f;
        float2 wo;
        if (m > 1) {
            float a2 = ds * CUDART_PI_F * (float)(lane & (m - 1)) / (float)m;
            float2 w; __sincosf(a2, &w.y, &w.x);
            wo = up ? w : make_float2(1.0f, 0.0f);
        }
#pragma unroll
        for (int k = 0; k < 8; k++) {
            float ox = __shfl_xor_sync(0xffffffffu, v[k].x, m);
            float oy = __shfl_xor_sync(0xffffffffu, v[k].y, m);
            float tx = fmaf(s, v[k].x, ox);
            float ty = fmaf(s, v[k].y, oy);
            if (m > 1) v[k] = cmul(make_float2(tx, ty), wo);
            else       v[k] = make_float2(tx, ty);
        }
    }
}

// Adjoint (unnormalized inverse) of fft256<1>: permuted in, natural out.
__device__ __forceinline__ void ifft256_adj(float2 v[8], int lane) {
#pragma unroll
    for (int m = 1; m <= 16; m <<= 1) {
        bool up = (lane & m) != 0;
        if (m > 1) {
            float a2 = CUDART_PI_F * (float)(lane & (m - 1)) / (float)m;
            float2 w; __sincosf(a2, &w.y, &w.x);
            float2 wo = up ? w : make_float2(1.0f, 0.0f);
#pragma unroll
            for (int k = 0; k < 8; k++) v[k] = cmul(v[k], wo);
        }
        float s = up ? -1.0f : 1.0f;
#pragma unroll
        for (int k = 0; k < 8; k++) {
            float ox = __shfl_xor_sync(0xffffffffu, v[k].x, m);
            float oy = __shfl_xor_sync(0xffffffffu, v[k].y, m);
            v[k].x = fmaf(s, v[k].x, ox);
            v[k].y = fmaf(s, v[k].y, oy);
        }
    }
    float ang = CUDART_PI_F * (float)lane * (1.0f / 128.0f);
    float2 w1; __sincosf(ang, &w1.y, &w1.x);
    float2 w2 = cmul(w1, w1);
    float2 w3 = cmul(w2, w1);
    float2 w4 = cmul(w2, w2);
    float2 w5 = cmul(w4, w1);
    float2 w6 = cmul(w3, w3);
    float2 w7 = cmul(w4, w3);
    v[1] = cmul(v[1], w1); v[2] = cmul(v[2], w2); v[3] = cmul(v[3], w3);
    v[4] = cmul(v[4], w4); v[5] = cmul(v[5], w5); v[6] = cmul(v[6], w6);
    v[7] = cmul(v[7], w7);

    fft8_slots<-1>(v);
}

// ---------------------------------------------------------------------------
// Pass 1: forward real row FFT, 2 rows packed, output transposed [img][wb][h]
// ---------------------------------------------------------------------------
__global__ void __launch_bounds__(256)
rowfft_kernel(const float* __restrict__ in, __half2* __restrict__ outF) {
    __shared__ float2 zbuf[8][264];
    int tid = threadIdx.x, lane = tid & 31, wrp = tid >> 5;
    size_t img = blockIdx.y;
    int row0 = blockIdx.x * 16;

    const float* pa = in + (img * HH + row0 + 2 * wrp) * (size_t)WW;
    const float* pb = pa + WW;
    float2 v[8];
#pragma unroll
    for (int j = 0; j < 8; j++)
        v[j] = make_float2(pa[lane + 32 * j], pb[lane + 32 * j]);

    fft256<1>(v, lane);

    int k1 = __brev((unsigned)lane) >> 27;
#pragma unroll
    for (int k2 = 0; k2 < 8; k2++) zbuf[wrp][k1 + 33 * k2] = v[k2];
    __syncthreads();

    for (int idx = tid; idx < WB * 16; idx += 256) {
        int r = idx & 15, k = idx >> 4;
        int p = r >> 1;
        int km = (256 - k) & 255;
        float2 Z  = zbuf[p][(k  & 7) * 33 + (k  >> 3)];
        float2 Zm = zbuf[p][(km & 7) * 33 + (km >> 3)];
        float2 o;
        if (r & 1) o = make_float2(0.5f * (Z.y + Zm.y), 0.5f * (Zm.x - Z.x));
        else       o = make_float2(0.5f * (Z.x + Zm.x), 0.5f * (Z.y - Zm.y));
        outF[(img * WB + k) * (size_t)HH + row0 + r] = f2h(o);
    }
}

// ---------------------------------------------------------------------------
// Pass 2: forward column FFT over h. Coalesced; stores permuted order.
// ---------------------------------------------------------------------------
__global__ void __launch_bounds__(512)
colfft_fwd_kernel(__half2* __restrict__ F) {
    int gid = blockIdx.x * 16 + (threadIdx.x >> 5);
    int lane = threadIdx.x & 31;
    __half2* p = F + (size_t)gid * HH;

    float2 v[8];
#pragma unroll
    for (int j = 0; j < 8; j++) v[j] = h2f(p[lane + 32 * j]);

    fft256<1>(v, lane);

#pragma unroll
    for (int k2 = 0; k2 < 8; k2++) p[k2 * 32 + lane] = f2h(v[k2]);
}

// ---------------------------------------------------------------------------
// Pass 4: inverse column FFT. Loads permuted, stores natural h.
// ---------------------------------------------------------------------------
__global__ void __launch_bounds__(512)
colfft_inv_kernel(__half2* __restrict__ F) {
    int gid = blockIdx.x * 16 + (threadIdx.x >> 5);
    int lane = threadIdx.x & 31;
    __half2* p = F + (size_t)gid * HH;

    float2 v[8];
#pragma unroll
    for (int k2 = 0; k2 < 8; k2++) v[k2] = h2f(p[k2 * 32 + lane]);

    ifft256_adj(v, lane);

#pragma unroll
    for (int j = 0; j < 8; j++) p[lane + 32 * j] = f2h(v[j]);
}

// ---------------------------------------------------------------------------
// Pass 3: per-bin channel contraction, 4b x 2o register tiling, fp32 smem.
// ---------------------------------------------------------------------------
#define XSTR 18
#define KSTR 34
__global__ void __launch_bounds__(512, 2)
binconv_kernel(const __half2* __restrict__ Xf, const __half2* __restrict__ Kf,
               __half2* __restrict__ Of) {
    extern __shared__ float2 sm[];
    float2* Xs = sm;
    float2* Ks = sm + 32 * 8 * XSTR;

    int tid = threadIdx.x;
    int wb = blockIdx.y;
    int h0 = blockIdx.x * 8;
    int hl = tid & 7;
    int sub = tid >> 3;

#pragma unroll
    for (int i = 0; i < 8; i++) {
        int img = i * 64 + sub;           // b*32 + c
        Xs[((img & 31) * 8 + hl) * XSTR + (img >> 5)] =
            h2f(Xf[((size_t)img * WB + wb) * HH + h0 + hl]);
    }
#pragma unroll
    for (int i = 0; i < 16; i++) {
        int img = i * 64 + sub;           // o*32 + c
        Ks[((img & 31) * 8 + hl) * KSTR + (img >> 5)] =
            h2f(Kf[((size_t)img * WB + wb) * HH + h0 + hl]);
    }
    __syncthreads();

    int bq = tid & 3;
    int q  = (tid >> 2) & 7;
    int op = tid >> 5;
    const float4* X4 = (const float4*)Xs;
    const float4* K4 = (const float4*)Ks;

    float2 acc[4][2];
#pragma unroll
    for (int bi = 0; bi < 4; bi++)
#pragma unroll
        for (int oi = 0; oi < 2; oi++) acc[bi][oi] = make_float2(0.f, 0.f);

#pragma unroll 4
    for (int c = 0; c < 32; c++) {
        int xrow = (c * 8 + q) * (XSTR / 2);
        int krow = (c * 8 + q) * (KSTR / 2);
        float4 xa = X4[xrow + 2 * bq];
        float4 xb = X4[xrow + 2 * bq + 1];
        float4 kv = K4[krow + op];
        float xr[4] = {xa.x, xa.z, xb.x, xb.z};
        float xi[4] = {xa.y, xa.w, xb.y, xb.w};
        float kr[2] = {kv.x, kv.z};
        float ki[2] = {kv.y, kv.w};
#pragma unroll
        for (int bi = 0; bi < 4; bi++)
#pragma unroll
            for (int oi = 0; oi < 2; oi++) {
                acc[bi][oi].x = fmaf(xr[bi], kr[oi], fmaf(-xi[bi], ki[oi], acc[bi][oi].x));
                acc[bi][oi].y = fmaf(xr[bi], ki[oi], fmaf( xi[bi], kr[oi], acc[bi][oi].y));
            }
    }

    int b0 = 4 * bq, o0 = 2 * op, h = h0 + q;
#pragma unroll
    for (int bi = 0; bi < 4; bi++)
#pragma unroll
        for (int oi = 0; oi < 2; oi++)
            Of[(((size_t)(b0 + bi) * NO + o0 + oi) * WB + wb) * HH + h] = f2h(acc[bi][oi]);
}

// ---------------------------------------------------------------------------
// Pass 5: inverse real row FFT (2 rows packed), un-transpose + 1/(H*W) scale.
// ---------------------------------------------------------------------------
__global__ void __launch_bounds__(256)
irow_kernel(const __half2* __restrict__ OF, float* __restrict__ out) {
    __shared__ float2 sbuf[WB * 17];
    int tid = threadIdx.x, lane = tid & 31, wrp = tid >> 5;
    size_t img = blockIdx.y;
    int row0 = blockIdx.x * 16;

    for (int idx = tid; idx < WB * 16; idx += 256) {
        int r = idx & 15, k = idx >> 4;
        sbuf[k * 17 + r] = h2f(OF[(img * WB + k) * (size_t)HH + row0 + r]);
    }
    __syncthreads();

    float2 v[8];
#pragma unroll
    for (int j = 0; j < 8; j++) {
        int k = lane + 32 * j;
        if (k <= 128) {
            float2 A  = sbuf[k * 17 + 2 * wrp];
            float2 Bv = sbuf[k * 17 + 2 * wrp + 1];
            v[j] = make_float2(A.x - Bv.y, A.y + Bv.x);
        } else {
            int km = 256 - k;
            float2 A  = sbuf[km * 17 + 2 * wrp];
            float2 Bv = sbuf[km * 17 + 2 * wrp + 1];
            v[j] = make_float2(A.x + Bv.y, Bv.x - A.y);
        }
    }

    fft256<-1>(v, lane);

    const float sc = 1.0f / 65536.0f;
    int base = 8 * (__brev((unsigned)lane) >> 27);
    float* oa = out + (img * HH + row0 + 2 * wrp) * (size_t)WW + base;
    float* ob = oa + WW;
    float4* oa4 = (float4*)oa; float4* ob4 = (float4*)ob;
#pragma unroll
    for (int qq = 0; qq < 2; qq++) {
        oa4[qq] = make_float4(v[4*qq].x * sc, v[4*qq+1].x * sc, v[4*qq+2].x * sc, v[4*qq+3].x * sc);
        ob4[qq] = make_float4(v[4*qq].y * sc, v[4*qq+1].y * sc, v[4*qq+2].y * sc, v[4*qq+3].y * sc);
    }
}

// ---------------------------------------------------------------------------
extern "C" void kernel_launch(void* const* d_in, const int* in_sizes, int n_in,
                              void* d_out, int out_size) {
    const float* x = (const float*)d_in[0];
    const float* w = (const float*)d_in[1];
    float* out = (float*)d_out;

    __half2 *xf, *kf, *of;
    cudaGetSymbolAddress((void**)&xf, g_Xf);
    cudaGetSymbolAddress((void**)&kf, g_Kf);
    cudaGetSymbolAddress((void**)&of, g_Of);

    rowfft_kernel<<<dim3(16, NB * NC), 256>>>(x, xf);
    rowfft_kernel<<<dim3(16, NO * NC), 256>>>(w, kf);

    colfft_fwd_kernel<<<(NB * NC * WB + 15) / 16, 512>>>(xf);
    colfft_fwd_kernel<<<(NO * NC * WB + 15) / 16, 512>>>(kf);

    size_t bsm = (size_t)(32 * 8 * (XSTR + KSTR)) * sizeof(float2);
    cudaFuncSetAttribute(binconv_kernel,
                         cudaFuncAttributeMaxDynamicSharedMemorySize, (int)bsm);
    binconv_kernel<<<dim3(32, WB), 512, bsm>>>(xf, kf, of);

    colfft_inv_kernel<<<(NB * NO * WB + 15) / 16, 512>>>(of);

    irow_kernel<<<dim3(16, NB * NO), 256>>>(of, out);
}

// round 6
// speedup vs baseline: 8.2686x; 1.0617x over previous
#include <cuda_runtime.h>
#include <cuda_fp16.h>
#include <math_constants.h>

#define NB 16
#define NC 32
#define NO 32
#define HH 256
#define WW 256
#define WB 129

// Frequency-domain scratch in fp16 (half2 = one complex), layout [img][wb][h];
// h is PERMUTED between forward and inverse column FFTs.
__device__ __half2 g_Xf[(size_t)NB * NC * WB * HH];
__device__ __half2 g_Kf[(size_t)NO * NC * WB * HH];
__device__ __half2 g_Of[(size_t)NB * NO * WB * HH];

// ---------------------------------------------------------------------------
// Packed complex: one fp32 (re, im) pair in a 64-bit register pair.
// ---------------------------------------------------------------------------
typedef unsigned long long cplx;

__device__ __forceinline__ cplx cpk(float x, float y) {
    cplx r; asm("mov.b64 %0, {%1, %2};" : "=l"(r) : "f"(x), "f"(y)); return r;
}
__device__ __forceinline__ float2 cup(cplx a) {
    float2 r; asm("mov.b64 {%0, %1}, %2;" : "=f"(r.x), "=f"(r.y) : "l"(a)); return r;
}
__device__ __forceinline__ cplx cadd2(cplx a, cplx b) {
    cplx r; asm("add.rn.f32x2 %0, %1, %2;" : "=l"(r) : "l"(a), "l"(b)); return r;
}
__device__ __forceinline__ cplx cmul2(cplx a, cplx b) {
    cplx r; asm("mul.rn.f32x2 %0, %1, %2;" : "=l"(r) : "l"(a), "l"(b)); return r;
}
__device__ __forceinline__ cplx cfma2(cplx a, cplx b, cplx c) {
    cplx r; asm("fma.rn.f32x2 %0, %1, %2, %3;" : "=l"(r) : "l"(a), "l"(b), "l"(c)); return r;
}
// complex multiply by scalar-held twiddle w: (a.x*w.x - a.y*w.y, a.y*w.x + a.x*w.y)
__device__ __forceinline__ cplx cmulw(cplx a, float2 w) {
    float2 t = cup(a);
    return cfma2(cpk(t.y, t.x), cpk(-w.y, w.y), cmul2(a, cpk(w.x, w.x)));
}
template <int DIR>
__device__ __forceinline__ cplx mulJp(cplx a) {  // *(-i) fwd, *(+i) inv
    float2 t = cup(a);
    return (DIR > 0) ? cpk(t.y, -t.x) : cpk(-t.y, t.x);
}
__device__ __forceinline__ float2 cmulf(float2 a, float2 b) {
    return make_float2(fmaf(a.x, b.x, -a.y * b.y), fmaf(a.x, b.y, a.y * b.x));
}
__device__ __forceinline__ float2 h2f(__half2 h) { return __half22float2(h); }
__device__ __forceinline__ __half2 f2h(float2 f) { return __floats2half2_rn(f.x, f.y); }

// ---------------------------------------------------------------------------
// FFT8 over register slots (natural in / natural out), e^{-i} for DIR=+1
// ---------------------------------------------------------------------------
template <int DIR>
__device__ __forceinline__ void fft8_slots(cplx v[8]) {
    const cplx N1 = cpk(-1.0f, -1.0f);
    const float ds = (DIR > 0) ? -1.0f : 1.0f;
    const float S = 0.70710678118654752f;
    cplx b0 = cadd2(v[0], v[4]), b1 = cfma2(v[4], N1, v[0]);
    cplx b2 = cadd2(v[2], v[6]), b3 = cfma2(v[6], N1, v[2]);
    cplx b4 = cadd2(v[1], v[5]), b5 = cfma2(v[5], N1, v[1]);
    cplx b6 = cadd2(v[3], v[7]), b7 = cfma2(v[7], N1, v[3]);
    cplx t  = mulJp<DIR>(b3);
    cplx c0 = cadd2(b0, b2), c2 = cfma2(b2, N1, b0);
    cplx c1 = cadd2(b1, t),  c3 = cfma2(t, N1, b1);
    t = mulJp<DIR>(b7);
    cplx c4 = cadd2(b4, b6), c6 = cfma2(b6, N1, b4);
    cplx c5 = cadd2(b5, t),  c7 = cfma2(t, N1, b5);
    const float2 W81 = make_float2(S, ds * S);
    const float2 W83 = make_float2(-S, ds * S);
    v[0] = cadd2(c0, c4); v[4] = cfma2(c4, N1, c0);
    t = cmulw(c5, W81);   v[1] = cadd2(c1, t); v[5] = cfma2(t, N1, c1);
    t = mulJp<DIR>(c6);   v[2] = cadd2(c2, t); v[6] = cfma2(t, N1, c2);
    t = cmulw(c7, W83);   v[3] = cadd2(c3, t); v[7] = cfma2(t, N1, c3);
}

// ---------------------------------------------------------------------------
// Forward register/shuffle FFT-256. Input v[j]=x[lane+32*j]. Output: lane
// holds X[8*br5(lane)+k2] in v[k2].
// ---------------------------------------------------------------------------
template <int DIR>
__device__ __forceinline__ void fft256(cplx v[8], int lane) {
    const float ds = (DIR > 0) ? -1.0f : 1.0f;
    fft8_slots<DIR>(v);

    float ang = ds * CUDART_PI_F * (float)lane * (1.0f / 128.0f);
    float2 w1; __sincosf(ang, &w1.y, &w1.x);
    float2 w2 = cmulf(w1, w1);
    float2 w3 = cmulf(w2, w1);
    float2 w4 = cmulf(w2, w2);
    float2 w5 = cmulf(w4, w1);
    float2 w6 = cmulf(w3, w3);
    float2 w7 = cmulf(w4, w3);
    v[1] = cmulw(v[1], w1); v[2] = cmulw(v[2], w2); v[3] = cmulw(v[3], w3);
    v[4] = cmulw(v[4], w4); v[5] = cmulw(v[5], w5); v[6] = cmulw(v[6], w6);
    v[7] = cmulw(v[7], w7);

#pragma unroll
    for (int m = 16; m >= 1; m >>= 1) {
        bool up = (lane & m) != 0;
        float s = up ? -1.0f : 1.0f;
        cplx s2 = cpk(s, s);
        cplx wxx, wmy;
        if (m > 1) {
            float a2 = ds * CUDART_PI_F * (float)(lane & (m - 1)) / (float)m;
            float2 w; __sincosf(a2, &w.y, &w.x);
            float2 wo = up ? w : make_float2(1.0f, 0.0f);
            wxx = cpk(wo.x, wo.x);
            wmy = cpk(-wo.y, wo.y);
        }
#pragma unroll
        for (int k = 0; k < 8; k++) {
            float2 t = cup(v[k]);
            float ox = __shfl_xor_sync(0xffffffffu, t.x, m);
            float oy = __shfl_xor_sync(0xffffffffu, t.y, m);
            cplx tt = cfma2(v[k], s2, cpk(ox, oy));
            if (m > 1) {
                float2 u = cup(tt);
                v[k] = cfma2(cpk(u.y, u.x), wmy, cmul2(tt, wxx));
            } else {
                v[k] = tt;
            }
        }
    }
}

// ---------------------------------------------------------------------------
// Adjoint (unnormalized inverse) of fft256<1>: permuted in, natural out.
// ---------------------------------------------------------------------------
__device__ __forceinline__ void ifft256_adj(cplx v[8], int lane) {
#pragma unroll
    for (int m = 1; m <= 16; m <<= 1) {
        bool up = (lane & m) != 0;
        float s = up ? -1.0f : 1.0f;
        cplx s2 = cpk(s, s);
        if (m > 1) {
            float a2 = CUDART_PI_F * (float)(lane & (m - 1)) / (float)m; // conj
            float2 w; __sincosf(a2, &w.y, &w.x);
            float2 wo = up ? w : make_float2(1.0f, 0.0f);
            cplx wxx = cpk(wo.x, wo.x);
            cplx wmy = cpk(-wo.y, wo.y);
#pragma unroll
            for (int k = 0; k < 8; k++) {
                float2 u = cup(v[k]);
                v[k] = cfma2(cpk(u.y, u.x), wmy, cmul2(v[k], wxx));
            }
        }
#pragma unroll
        for (int k = 0; k < 8; k++) {
            float2 t = cup(v[k]);
            float ox = __shfl_xor_sync(0xffffffffu, t.x, m);
            float oy = __shfl_xor_sync(0xffffffffu, t.y, m);
            v[k] = cfma2(v[k], s2, cpk(ox, oy));
        }
    }
    // conj inter-factor twiddles
    float ang = CUDART_PI_F * (float)lane * (1.0f / 128.0f);
    float2 w1; __sincosf(ang, &w1.y, &w1.x);
    float2 w2 = cmulf(w1, w1);
    float2 w3 = cmulf(w2, w1);
    float2 w4 = cmulf(w2, w2);
    float2 w5 = cmulf(w4, w1);
    float2 w6 = cmulf(w3, w3);
    float2 w7 = cmulf(w4, w3);
    v[1] = cmulw(v[1], w1); v[2] = cmulw(v[2], w2); v[3] = cmulw(v[3], w3);
    v[4] = cmulw(v[4], w4); v[5] = cmulw(v[5], w5); v[6] = cmulw(v[6], w6);
    v[7] = cmulw(v[7], w7);

    fft8_slots<-1>(v);
}

// ---------------------------------------------------------------------------
// Pass 1: forward real row FFT, 2 rows packed, output transposed [img][wb][h]
// ---------------------------------------------------------------------------
__global__ void __launch_bounds__(256)
rowfft_kernel(const float* __restrict__ in, __half2* __restrict__ outF) {
    __shared__ float2 zbuf[8][264];
    int tid = threadIdx.x, lane = tid & 31, wrp = tid >> 5;
    size_t img = blockIdx.y;
    int row0 = blockIdx.x * 16;

    const float* pa = in + (img * HH + row0 + 2 * wrp) * (size_t)WW;
    const float* pb = pa + WW;
    cplx v[8];
#pragma unroll
    for (int j = 0; j < 8; j++)
        v[j] = cpk(pa[lane + 32 * j], pb[lane + 32 * j]);

    fft256<1>(v, lane);

    int k1 = __brev((unsigned)lane) >> 27;
#pragma unroll
    for (int k2 = 0; k2 < 8; k2++) zbuf[wrp][k1 + 33 * k2] = cup(v[k2]);
    __syncthreads();

    for (int idx = tid; idx < WB * 16; idx += 256) {
        int r = idx & 15, k = idx >> 4;
        int p = r >> 1;
        int km = (256 - k) & 255;
        float2 Z  = zbuf[p][(k  & 7) * 33 + (k  >> 3)];
        float2 Zm = zbuf[p][(km & 7) * 33 + (km >> 3)];
        float2 o;
        if (r & 1) o = make_float2(0.5f * (Z.y + Zm.y), 0.5f * (Zm.x - Z.x));
        else       o = make_float2(0.5f * (Z.x + Zm.x), 0.5f * (Z.y - Zm.y));
        outF[(img * WB + k) * (size_t)HH + row0 + r] = f2h(o);
    }
}

// ---------------------------------------------------------------------------
// Pass 2: forward column FFT over h. Coalesced; stores permuted order.
// ---------------------------------------------------------------------------
__global__ void __launch_bounds__(512)
colfft_fwd_kernel(__half2* __restrict__ F) {
    int gid = blockIdx.x * 16 + (threadIdx.x >> 5);
    int lane = threadIdx.x & 31;
    __half2* p = F + (size_t)gid * HH;

    cplx v[8];
#pragma unroll
    for (int j = 0; j < 8; j++) {
        float2 f = h2f(p[lane + 32 * j]);
        v[j] = cpk(f.x, f.y);
    }

    fft256<1>(v, lane);

#pragma unroll
    for (int k2 = 0; k2 < 8; k2++) p[k2 * 32 + lane] = f2h(cup(v[k2]));
}

// ---------------------------------------------------------------------------
// Pass 4: inverse column FFT. Loads permuted, stores natural h.
// ---------------------------------------------------------------------------
__global__ void __launch_bounds__(512)
colfft_inv_kernel(__half2* __restrict__ F) {
    int gid = blockIdx.x * 16 + (threadIdx.x >> 5);
    int lane = threadIdx.x & 31;
    __half2* p = F + (size_t)gid * HH;

    cplx v[8];
#pragma unroll
    for (int k2 = 0; k2 < 8; k2++) {
        float2 f = h2f(p[k2 * 32 + lane]);
        v[k2] = cpk(f.x, f.y);
    }

    ifft256_adj(v, lane);

#pragma unroll
    for (int j = 0; j < 8; j++) p[lane + 32 * j] = f2h(cup(v[j]));
}

// ---------------------------------------------------------------------------
// Pass 3: per-bin channel contraction, 4b x 2o register tiling, fp32 smem.
// ---------------------------------------------------------------------------
#define XSTR 18
#define KSTR 34
__global__ void __launch_bounds__(512, 2)
binconv_kernel(const __half2* __restrict__ Xf, const __half2* __restrict__ Kf,
               __half2* __restrict__ Of) {
    extern __shared__ float2 sm[];
    float2* Xs = sm;
    float2* Ks = sm + 32 * 8 * XSTR;

    int tid = threadIdx.x;
    int wb = blockIdx.y;
    int h0 = blockIdx.x * 8;
    int hl = tid & 7;
    int sub = tid >> 3;

#pragma unroll
    for (int i = 0; i < 8; i++) {
        int img = i * 64 + sub;           // b*32 + c
        Xs[((img & 31) * 8 + hl) * XSTR + (img >> 5)] =
            h2f(Xf[((size_t)img * WB + wb) * HH + h0 + hl]);
    }
#pragma unroll
    for (int i = 0; i < 16; i++) {
        int img = i * 64 + sub;           // o*32 + c
        Ks[((img & 31) * 8 + hl) * KSTR + (img >> 5)] =
            h2f(Kf[((size_t)img * WB + wb) * HH + h0 + hl]);
    }
    __syncthreads();

    int bq = tid & 3;
    int q  = (tid >> 2) & 7;
    int op = tid >> 5;
    const float4* X4 = (const float4*)Xs;
    const float4* K4 = (const float4*)Ks;

    float2 acc[4][2];
#pragma unroll
    for (int bi = 0; bi < 4; bi++)
#pragma unroll
        for (int oi = 0; oi < 2; oi++) acc[bi][oi] = make_float2(0.f, 0.f);

#pragma unroll 4
    for (int c = 0; c < 32; c++) {
        int xrow = (c * 8 + q) * (XSTR / 2);
        int krow = (c * 8 + q) * (KSTR / 2);
        float4 xa = X4[xrow + 2 * bq];
        float4 xb = X4[xrow + 2 * bq + 1];
        float4 kv = K4[krow + op];
        float xr[4] = {xa.x, xa.z, xb.x, xb.z};
        float xi[4] = {xa.y, xa.w, xb.y, xb.w};
        float kr[2] = {kv.x, kv.z};
        float ki[2] = {kv.y, kv.w};
#pragma unroll
        for (int bi = 0; bi < 4; bi++)
#pragma unroll
            for (int oi = 0; oi < 2; oi++) {
                acc[bi][oi].x = fmaf(xr[bi], kr[oi], fmaf(-xi[bi], ki[oi], acc[bi][oi].x));
                acc[bi][oi].y = fmaf(xr[bi], ki[oi], fmaf( xi[bi], kr[oi], acc[bi][oi].y));
            }
    }

    int b0 = 4 * bq, o0 = 2 * op, h = h0 + q;
#pragma unroll
    for (int bi = 0; bi < 4; bi++)
#pragma unroll
        for (int oi = 0; oi < 2; oi++)
            Of[(((size_t)(b0 + bi) * NO + o0 + oi) * WB + wb) * HH + h] = f2h(acc[bi][oi]);
}

// ---------------------------------------------------------------------------
// Pass 5: inverse real row FFT (2 rows packed), un-transpose + 1/(H*W) scale.
// ---------------------------------------------------------------------------
__global__ void __launch_bounds__(256)
irow_kernel(const __half2* __restrict__ OF, float* __restrict__ out) {
    __shared__ float2 sbuf[WB * 17];
    int tid = threadIdx.x, lane = tid & 31, wrp = tid >> 5;
    size_t img = blockIdx.y;
    int row0 = blockIdx.x * 16;

    for (int idx = tid; idx < WB * 16; idx += 256) {
        int r = idx & 15, k = idx >> 4;
        sbuf[k * 17 + r] = h2f(OF[(img * WB + k) * (size_t)HH + row0 + r]);
    }
    __syncthreads();

    cplx v[8];
#pragma unroll
    for (int j = 0; j < 8; j++) {
        int k = lane + 32 * j;
        float2 r;
        if (k <= 128) {
            float2 A  = sbuf[k * 17 + 2 * wrp];
            float2 Bv = sbuf[k * 17 + 2 * wrp + 1];
            r = make_float2(A.x - Bv.y, A.y + Bv.x);
        } else {
            int km = 256 - k;
            float2 A  = sbuf[km * 17 + 2 * wrp];
            float2 Bv = sbuf[km * 17 + 2 * wrp + 1];
            r = make_float2(A.x + Bv.y, Bv.x - A.y);
        }
        v[j] = cpk(r.x, r.y);
    }

    fft256<-1>(v, lane);

    const float sc = 1.0f / 65536.0f;
    int base = 8 * (__brev((unsigned)lane) >> 27);
    float* oa = out + (img * HH + row0 + 2 * wrp) * (size_t)WW + base;
    float* ob = oa + WW;
    float4* oa4 = (float4*)oa; float4* ob4 = (float4*)ob;
    float2 f[8];
#pragma unroll
    for (int j = 0; j < 8; j++) f[j] = cup(v[j]);
#pragma unroll
    for (int qq = 0; qq < 2; qq++) {
        oa4[qq] = make_float4(f[4*qq].x * sc, f[4*qq+1].x * sc, f[4*qq+2].x * sc, f[4*qq+3].x * sc);
        ob4[qq] = make_float4(f[4*qq].y * sc, f[4*qq+1].y * sc, f[4*qq+2].y * sc, f[4*qq+3].y * sc);
    }
}

// ---------------------------------------------------------------------------
extern "C" void kernel_launch(void* const* d_in, const int* in_sizes, int n_in,
                              void* d_out, int out_size) {
    const float* x = (const float*)d_in[0];
    const float* w = (const float*)d_in[1];
    float* out = (float*)d_out;

    __half2 *xf, *kf, *of;
    cudaGetSymbolAddress((void**)&xf, g_Xf);
    cudaGetSymbolAddress((void**)&kf, g_Kf);
    cudaGetSymbolAddress((void**)&of, g_Of);

    rowfft_kernel<<<dim3(16, NB * NC), 256>>>(x, xf);
    rowfft_kernel<<<dim3(16, NO * NC), 256>>>(w, kf);

    colfft_fwd_kernel<<<(NB * NC * WB + 15) / 16, 512>>>(xf);
    colfft_fwd_kernel<<<(NO * NC * WB + 15) / 16, 512>>>(kf);

    size_t bsm = (size_t)(32 * 8 * (XSTR + KSTR)) * sizeof(float2);
    cudaFuncSetAttribute(binconv_kernel,
                         cudaFuncAttributeMaxDynamicSharedMemorySize, (int)bsm);
    binconv_kernel<<<dim3(32, WB), 512, bsm>>>(xf, kf, of);

    colfft_inv_kernel<<<(NB * NO * WB + 15) / 16, 512>>>(of);

    irow_kernel<<<dim3(16, NB * NO), 256>>>(of, out);
}